// round 5
// baseline (speedup 1.0000x reference)
#include <cuda_runtime.h>
#include <cuda_fp16.h>
#include <cstdint>
#include <cstddef>

#define MM    3
#define NN    100000
#define DIN   128
#define DH    64
#define EDGES 1600000
#define NSEG  (MM * NN)                 // 300000 segments (m, dst)
#define SCAN_TILE 1024
#define NBLK  ((NSEG + SCAN_TILE - 1) / SCAN_TILE)   // 293

// ---------------- scratch (device globals; no allocations) ----------------
__device__ __half g_proj[(size_t)MM * NN * DH];  // 38.4 MB [m][n][h] fp16
__device__ __half g_hn  [(size_t)NN * MM * DH];  // 38.4 MB [n][m][h] fp16
__device__ int    g_count [NSEG];
__device__ int    g_cursor[NSEG];
__device__ int    g_eidx[(size_t)MM * EDGES];
__device__ unsigned short g_rank[(size_t)MM * EDGES];
__device__ int    g_bsum[NBLK];
__device__ float  g_logits[MM];

// packed f32x2 FMA (FFMA2) — 2x fp32 FMA throughput, only reachable via PTX
__device__ __forceinline__ float2 ffma2(float2 a, float2 b, float2 c) {
    unsigned long long au = *reinterpret_cast<unsigned long long*>(&a);
    unsigned long long bu = *reinterpret_cast<unsigned long long*>(&b);
    unsigned long long cu = *reinterpret_cast<unsigned long long*>(&c);
    unsigned long long du;
    asm("fma.rn.f32x2 %0, %1, %2, %3;" : "=l"(du) : "l"(au), "l"(bu), "l"(cu));
    return *reinterpret_cast<float2*>(&du);
}

// ---------------- K1: proj[m] = feats[m] @ W[m]  (fp32 math, fp16 store) ---
#define FPAD 36
__global__ __launch_bounds__(128) void k_proj(const float* __restrict__ feats,
                                              const float* __restrict__ W) {
    __shared__ float sF[256 * FPAD];
    __shared__ float sW[32 * 64];

    const int m     = blockIdx.y;
    const int node0 = blockIdx.x * 256;
    const int t  = threadIdx.x;
    const int rg = t >> 2;
    const int cg = t & 3;

    const float* fbase = feats + (size_t)m * NN * DIN;
    const float* wbase = W     + (size_t)m * DIN * DH;

    float2 acc[8][8];
    #pragma unroll
    for (int i = 0; i < 8; i++)
        #pragma unroll
        for (int j = 0; j < 8; j++) acc[i][j] = make_float2(0.f, 0.f);

    for (int kt = 0; kt < DIN; kt += 32) {
        __syncthreads();
        #pragma unroll
        for (int it = 0; it < 16; it++) {
            int idx = t + 128 * it;
            int row = idx >> 3;
            int k4  = idx & 7;
            int gn  = node0 + row;
            float4 v = make_float4(0.f, 0.f, 0.f, 0.f);
            if (gn < NN)
                v = *(const float4*)(fbase + (size_t)gn * DIN + kt + k4 * 4);
            *(float4*)&sF[row * FPAD + k4 * 4] = v;
        }
        #pragma unroll
        for (int it = 0; it < 4; it++) {
            int idx = t + 128 * it;
            ((float4*)sW)[idx] = ((const float4*)(wbase + (size_t)kt * DH))[idx];
        }
        __syncthreads();

        #pragma unroll
        for (int k = 0; k < 32; k++) {
            float f[8];
            #pragma unroll
            for (int i = 0; i < 8; i++) f[i] = sF[(rg + 32 * i) * FPAD + k];
            float4 w0 = *(const float4*)&sW[k * 64 + cg * 16 + 0];
            float4 w1 = *(const float4*)&sW[k * 64 + cg * 16 + 4];
            float4 w2 = *(const float4*)&sW[k * 64 + cg * 16 + 8];
            float4 w3 = *(const float4*)&sW[k * 64 + cg * 16 + 12];
            float2 wv[8] = { {w0.x,w0.y},{w0.z,w0.w},{w1.x,w1.y},{w1.z,w1.w},
                             {w2.x,w2.y},{w2.z,w2.w},{w3.x,w3.y},{w3.z,w3.w} };
            #pragma unroll
            for (int i = 0; i < 8; i++) {
                float2 fi = make_float2(f[i], f[i]);
                #pragma unroll
                for (int j = 0; j < 8; j++)
                    acc[i][j] = ffma2(fi, wv[j], acc[i][j]);
            }
        }
    }

    __half* pbase = g_proj + (size_t)m * NN * DH;
    #pragma unroll
    for (int i = 0; i < 8; i++) {
        int n = node0 + rg + 32 * i;
        if (n < NN) {
            __half2* prow = (__half2*)(pbase + (size_t)n * DH + cg * 16);
            union { __half2 h[4]; uint4 u; } pk0, pk1;
            #pragma unroll
            for (int j = 0; j < 4; j++)
                pk0.h[j] = __floats2half2_rn(acc[i][j].x, acc[i][j].y);
            #pragma unroll
            for (int j = 0; j < 4; j++)
                pk1.h[j] = __floats2half2_rn(acc[i][4 + j].x, acc[i][4 + j].y);
            *(uint4*)prow       = pk0.u;
            *((uint4*)prow + 1) = pk1.u;
        }
    }
}

// ---------------- E1: histogram of (m, dst) + per-edge rank ----------------
__global__ void k_hist(const int* __restrict__ dst) {
    int e = blockIdx.x * blockDim.x + threadIdx.x;
    if (e >= EDGES) return;
    int m = blockIdx.y;
    int d = __ldg(dst + (size_t)m * EDGES + e);
    int r = atomicAdd(&g_count[m * NN + d], 1);
    g_rank[(size_t)m * EDGES + e] = (unsigned short)r;
}

// ---------------- E2: two-phase exclusive scan ----------------
__global__ __launch_bounds__(256) void k_scanA() {
    __shared__ int wsum[8];
    const int t = threadIdx.x;
    const long base = (long)blockIdx.x * SCAN_TILE + t * 4;
    int v[4];
    #pragma unroll
    for (int i = 0; i < 4; i++) v[i] = (base + i < NSEG) ? g_count[base + i] : 0;
    int tsum = v[0] + v[1] + v[2] + v[3];

    const int lane = t & 31, w = t >> 5;
    int x = tsum;
    #pragma unroll
    for (int o = 1; o < 32; o <<= 1) {
        int y = __shfl_up_sync(0xffffffffu, x, o);
        if (lane >= o) x += y;
    }
    if (lane == 31) wsum[w] = x;
    __syncthreads();
    if (t < 8) {
        int y = wsum[t];
        #pragma unroll
        for (int o = 1; o < 8; o <<= 1) {
            int z = __shfl_up_sync(0x000000ffu, y, o);
            if (t >= o) y += z;
        }
        wsum[t] = y;
    }
    __syncthreads();
    int run = ((w > 0) ? wsum[w - 1] : 0) + x - tsum;
    #pragma unroll
    for (int i = 0; i < 4; i++) {
        if (base + i < NSEG) g_cursor[base + i] = run;
        run += v[i];
    }
    if (t == 255) g_bsum[blockIdx.x] = wsum[7];
}

__global__ __launch_bounds__(512) void k_scanB() {
    __shared__ int a[512];
    const int t = threadIdx.x;
    int v = (t < NBLK) ? g_bsum[t] : 0;
    a[t] = v;
    __syncthreads();
    #pragma unroll
    for (int o = 1; o < 512; o <<= 1) {
        int x = (t >= o) ? a[t - o] : 0;
        __syncthreads();
        a[t] += x;
        __syncthreads();
    }
    if (t < NBLK) g_bsum[t] = a[t] - v;
}

// ---------------- E3: scatter src ids into CSR order (no atomics) ----------
__global__ void k_scatter(const int* __restrict__ src, const int* __restrict__ dst) {
    int e = blockIdx.x * blockDim.x + threadIdx.x;
    if (e >= EDGES) return;
    int m = blockIdx.y;
    int s   = __ldg(src + (size_t)m * EDGES + e);
    int d   = __ldg(dst + (size_t)m * EDGES + e);
    int rk  = (int)__ldg(&g_rank[(size_t)m * EDGES + e]);
    int seg = m * NN + d;
    int pos = __ldg(&g_cursor[seg]) + __ldg(&g_bsum[seg >> 10]) + rk;
    g_eidx[pos] = s;
}

// ---------------- FUSED: gather-reduce + prelu + hn write + GEMM + logits --
// 256 threads, 256 segments/block. Phase 1: 8 lanes/segment gather into sH.
// Phase 2: 256x64 @ 64x64 GEMM (tile 4 rows x 16 cols). Phase 3: tanh+logits.
#define HPAD 68
__global__ __launch_bounds__(256) void k_fused(const float* __restrict__ b,
                                               const float* __restrict__ prelu_a,
                                               const float* __restrict__ fc_W,
                                               const float* __restrict__ fc_b,
                                               const float* __restrict__ attn) {
    extern __shared__ float dynsm[];
    float* sH = dynsm;                 // 256 x HPAD = 69632 B
    float* sW = dynsm + 256 * HPAD;    // 64 x 64   = 16384 B
    __shared__ float sPart[3];

    const int t = threadIdx.x;
    const long g0 = (long)blockIdx.x * 256;

    if (t < 3) sPart[t] = 0.f;

    // fc_W: 1024 float4 / 256 thr = 4 each
    #pragma unroll
    for (int it = 0; it < 4; it++) {
        int idx = t + 256 * it;
        ((float4*)sW)[idx] = ((const float4*)fc_W)[idx];
    }

    // ---- Phase 1: gather-reduce. task = (segment-local, lane), 8 per thread.
    #pragma unroll 1
    for (int it = 0; it < 8; it++) {
        int task = t + 256 * it;
        int segl = task >> 3;
        int lane = task & 7;
        long gid = g0 + segl;

        float acc[8] = {0.f,0.f,0.f,0.f,0.f,0.f,0.f,0.f};
        if (gid < NSEG) {
            int m = (int)(gid / NN);
            int cnt   = __ldg(&g_count[gid]);
            int start = __ldg(&g_cursor[gid]) + __ldg(&g_bsum[gid >> 10]);
            int end   = start + cnt;
            const uint4* pb = (const uint4*)g_proj + (size_t)m * NN * 8;

            int j = start;
            for (; j + 1 < end; j += 2) {        // unroll-2: 2 independent chains
                int s0 = __ldg(&g_eidx[j]);
                int s1 = __ldg(&g_eidx[j + 1]);
                uint4 v0 = __ldg(&pb[(size_t)s0 * 8 + lane]);
                uint4 v1 = __ldg(&pb[(size_t)s1 * 8 + lane]);
                float2 f;
                f = __half22float2(*(__half2*)&v0.x); acc[0]+=f.x; acc[1]+=f.y;
                f = __half22float2(*(__half2*)&v0.y); acc[2]+=f.x; acc[3]+=f.y;
                f = __half22float2(*(__half2*)&v0.z); acc[4]+=f.x; acc[5]+=f.y;
                f = __half22float2(*(__half2*)&v0.w); acc[6]+=f.x; acc[7]+=f.y;
                f = __half22float2(*(__half2*)&v1.x); acc[0]+=f.x; acc[1]+=f.y;
                f = __half22float2(*(__half2*)&v1.y); acc[2]+=f.x; acc[3]+=f.y;
                f = __half22float2(*(__half2*)&v1.z); acc[4]+=f.x; acc[5]+=f.y;
                f = __half22float2(*(__half2*)&v1.w); acc[6]+=f.x; acc[7]+=f.y;
            }
            if (j < end) {
                int s0 = __ldg(&g_eidx[j]);
                uint4 v0 = __ldg(&pb[(size_t)s0 * 8 + lane]);
                float2 f;
                f = __half22float2(*(__half2*)&v0.x); acc[0]+=f.x; acc[1]+=f.y;
                f = __half22float2(*(__half2*)&v0.y); acc[2]+=f.x; acc[3]+=f.y;
                f = __half22float2(*(__half2*)&v0.z); acc[4]+=f.x; acc[5]+=f.y;
                f = __half22float2(*(__half2*)&v0.w); acc[6]+=f.x; acc[7]+=f.y;
            }

            float inv   = 1.0f / fmaxf((float)cnt, 1.0f);
            float alpha = __ldg(prelu_a + m);
            const float* bp = b + m * DH + lane * 8;
            #pragma unroll
            for (int c = 0; c < 8; c++) {
                float x = acc[c] * inv + __ldg(bp + c);
                acc[c] = x > 0.f ? x : alpha * x;
            }
            // write hn (fp16) for k_combine
            int n = (int)(gid % NN);
            union { __half2 p[4]; uint4 u; } pk;
            #pragma unroll
            for (int c = 0; c < 4; c++)
                pk.p[c] = __floats2half2_rn(acc[2*c], acc[2*c+1]);
            ((uint4*)(g_hn + ((size_t)n * MM + m) * DH))[lane] = pk.u;
        }
        // stage into smem tile (zeros for out-of-range rows)
        float* dstp = &sH[segl * HPAD + lane * 8];
        *(float4*)dstp       = make_float4(acc[0], acc[1], acc[2], acc[3]);
        *(float4*)(dstp + 4) = make_float4(acc[4], acc[5], acc[6], acc[7]);
    }
    __syncthreads();

    // ---- Phase 2: GEMM 256x64x64, thread tile 4 rows (stride 64) x 16 cols.
    const int rg = t >> 2;      // 0..63
    const int cg = t & 3;

    float2 acc2[4][8];
    #pragma unroll
    for (int i = 0; i < 4; i++)
        #pragma unroll
        for (int j = 0; j < 8; j++) acc2[i][j] = make_float2(0.f, 0.f);

    #pragma unroll 8
    for (int k = 0; k < DH; k++) {
        float f[4];
        #pragma unroll
        for (int i = 0; i < 4; i++) f[i] = sH[(rg + 64 * i) * HPAD + k];
        float4 w0 = *(const float4*)&sW[k * 64 + cg * 16 + 0];
        float4 w1 = *(const float4*)&sW[k * 64 + cg * 16 + 4];
        float4 w2 = *(const float4*)&sW[k * 64 + cg * 16 + 8];
        float4 w3 = *(const float4*)&sW[k * 64 + cg * 16 + 12];
        float2 wv[8] = { {w0.x,w0.y},{w0.z,w0.w},{w1.x,w1.y},{w1.z,w1.w},
                         {w2.x,w2.y},{w2.z,w2.w},{w3.x,w3.y},{w3.z,w3.w} };
        #pragma unroll
        for (int i = 0; i < 4; i++) {
            float2 fi = make_float2(f[i], f[i]);
            #pragma unroll
            for (int j = 0; j < 8; j++)
                acc2[i][j] = ffma2(fi, wv[j], acc2[i][j]);
        }
    }

    // ---- Phase 3: tanh + attn dot + per-m logit partials
    const float2* fb2 = (const float2*)fc_b;
    const float2* av2 = (const float2*)attn;
    float c0 = 0.f, c1 = 0.f, c2 = 0.f;
    #pragma unroll
    for (int i = 0; i < 4; i++) {
        long gid = g0 + rg + 64 * i;
        float ci = 0.f;
        #pragma unroll
        for (int j = 0; j < 8; j++) {
            float2 bb = __ldg(fb2 + cg * 8 + j);
            float2 aa = __ldg(av2 + cg * 8 + j);
            ci += tanhf(acc2[i][j].x + bb.x) * aa.x
                + tanhf(acc2[i][j].y + bb.y) * aa.y;
        }
        ci += __shfl_xor_sync(0xffffffffu, ci, 1);
        ci += __shfl_xor_sync(0xffffffffu, ci, 2);
        if (cg == 0 && gid < (long)NSEG) {
            int mi = (int)(gid / NN);
            if (mi == 0) c0 += ci; else if (mi == 1) c1 += ci; else c2 += ci;
        }
    }
    if (cg == 0) {
        if (c0 != 0.f) atomicAdd(&sPart[0], c0);
        if (c1 != 0.f) atomicAdd(&sPart[1], c1);
        if (c2 != 0.f) atomicAdd(&sPart[2], c2);
    }
    __syncthreads();
    if (t < 3) atomicAdd(&g_logits[t], sPart[t] * (1.0f / (float)NN));
}

// ---------------- K5: softmax(logits) + z = sum_m beta_m * hn[:,m,:] -------
__global__ void k_combine(float* __restrict__ out) {
    const long tid = (long)blockIdx.x * blockDim.x + threadIdx.x;
    if (tid >= (long)NN * 8) return;
    const int  q = (int)(tid & 7);
    const long n = tid >> 3;

    float l0 = g_logits[0], l1 = g_logits[1], l2 = g_logits[2];
    float mx = fmaxf(l0, fmaxf(l1, l2));
    float e0 = __expf(l0 - mx), e1 = __expf(l1 - mx), e2 = __expf(l2 - mx);
    float is = 1.0f / (e0 + e1 + e2);
    float b0 = e0 * is, b1 = e1 * is, b2 = e2 * is;

    const uint4* r = (const uint4*)(g_hn + (size_t)n * (MM * DH)) + q;
    uint4 u0 = __ldg(r), u1 = __ldg(r + 8), u2 = __ldg(r + 16);

    float o[8];
    #pragma unroll
    for (int c = 0; c < 4; c++) {
        float2 f0 = __half22float2(((const __half2*)&u0)[c]);
        float2 f1 = __half22float2(((const __half2*)&u1)[c]);
        float2 f2 = __half22float2(((const __half2*)&u2)[c]);
        o[2*c]   = b0 * f0.x + b1 * f1.x + b2 * f2.x;
        o[2*c+1] = b0 * f0.y + b1 * f1.y + b2 * f2.y;
    }
    float* op = out + (size_t)n * DH + q * 8;
    *(float4*)op       = make_float4(o[0], o[1], o[2], o[3]);
    *(float4*)(op + 4) = make_float4(o[4], o[5], o[6], o[7]);
}

// ---------------- launcher (fork-join: sort pipeline ∥ proj) ----------------
static cudaStream_t s_side = nullptr;
static cudaEvent_t  s_evFork = nullptr, s_evJoin = nullptr;

extern "C" void kernel_launch(void* const* d_in, const int* in_sizes, int n_in,
                              void* d_out, int out_size) {
    const float* feats   = (const float*)d_in[0];
    const int*   src     = (const int*)  d_in[1];
    const int*   dst     = (const int*)  d_in[2];
    const float* W       = (const float*)d_in[3];
    const float* b       = (const float*)d_in[4];
    const float* prelu_a = (const float*)d_in[5];
    const float* fc_W    = (const float*)d_in[6];
    const float* fc_b    = (const float*)d_in[7];
    const float* attn    = (const float*)d_in[8];
    float* out = (float*)d_out;

    if (!s_side) {
        cudaStreamCreateWithFlags(&s_side, cudaStreamNonBlocking);
        cudaEventCreateWithFlags(&s_evFork, cudaEventDisableTiming);
        cudaEventCreateWithFlags(&s_evJoin, cudaEventDisableTiming);
    }

    void *p_cnt, *p_log;
    cudaGetSymbolAddress(&p_cnt, g_count);
    cudaGetSymbolAddress(&p_log, g_logits);

    const int fused_smem = 256 * HPAD * 4 + 64 * 64 * 4;   // 86016
    cudaFuncSetAttribute(k_fused,
                         cudaFuncAttributeMaxDynamicSharedMemorySize, fused_smem);

    // fork: sort pipeline on side stream
    cudaEventRecord(s_evFork, 0);
    cudaStreamWaitEvent(s_side, s_evFork, 0);

    cudaMemsetAsync(p_cnt, 0, sizeof(int) * NSEG, s_side);
    dim3 ge((EDGES + 255) / 256, MM);
    k_hist   <<<ge, 256, 0, s_side>>>(dst);
    k_scanA  <<<NBLK, 256, 0, s_side>>>();
    k_scanB  <<<1, 512, 0, s_side>>>();
    k_scatter<<<ge, 256, 0, s_side>>>(src, dst);
    cudaEventRecord(s_evJoin, s_side);

    // main stream: projection GEMM (+ logits clear)
    cudaMemsetAsync(p_log, 0, sizeof(float) * MM, 0);
    dim3 g1((NN + 255) / 256, MM);
    k_proj<<<g1, 128>>>(feats, W);

    // join, then fused aggregate+attn -> combine
    cudaStreamWaitEvent(0, s_evJoin, 0);

    k_fused<<<(unsigned)((NSEG + 255) / 256), 256, fused_smem>>>(b, prelu_a,
                                                                 fc_W, fc_b, attn);

    k_combine<<<(unsigned)(((long)NN * 8 + 255) / 256), 256>>>(out);
}

// round 6
// speedup vs baseline: 1.1645x; 1.1645x over previous
#include <cuda_runtime.h>
#include <cuda_fp16.h>
#include <cstdint>
#include <cstddef>

#define MM    3
#define NN    100000
#define DIN   128
#define DH    64
#define EDGES 1600000
#define NSEG  (MM * NN)                 // 300000 segments (m, dst)
#define SCAN_TILE 1024
#define NBLK  ((NSEG + SCAN_TILE - 1) / SCAN_TILE)   // 293

// ---------------- scratch (device globals; no allocations) ----------------
__device__ __half g_proj[(size_t)MM * NN * DH];  // 38.4 MB [m][n][h] fp16
__device__ __half g_hn  [(size_t)NN * MM * DH];  // 38.4 MB [n][m][h] fp16
__device__ int    g_count [NSEG];
__device__ int    g_cursor[NSEG];
__device__ int    g_eidx[(size_t)MM * EDGES];
__device__ unsigned short g_rank[(size_t)MM * EDGES];
__device__ int    g_bsum[NBLK];
__device__ float  g_logits[MM];

// packed f32x2 FMA (FFMA2) — 2x fp32 FMA throughput, only reachable via PTX
__device__ __forceinline__ float2 ffma2(float2 a, float2 b, float2 c) {
    unsigned long long au = *reinterpret_cast<unsigned long long*>(&a);
    unsigned long long bu = *reinterpret_cast<unsigned long long*>(&b);
    unsigned long long cu = *reinterpret_cast<unsigned long long*>(&c);
    unsigned long long du;
    asm("fma.rn.f32x2 %0, %1, %2, %3;" : "=l"(du) : "l"(au), "l"(bu), "l"(cu));
    return *reinterpret_cast<float2*>(&du);
}

// ---------------- K1: proj[m] = feats[m] @ W[m]  (fp32 math, fp16 store) ---
#define FPAD 36
__global__ __launch_bounds__(128) void k_proj(const float* __restrict__ feats,
                                              const float* __restrict__ W) {
    __shared__ float sF[256 * FPAD];
    __shared__ float sW[32 * 64];

    const int m     = blockIdx.y;
    const int node0 = blockIdx.x * 256;
    const int t  = threadIdx.x;
    const int rg = t >> 2;
    const int cg = t & 3;

    const float* fbase = feats + (size_t)m * NN * DIN;
    const float* wbase = W     + (size_t)m * DIN * DH;

    float2 acc[8][8];
    #pragma unroll
    for (int i = 0; i < 8; i++)
        #pragma unroll
        for (int j = 0; j < 8; j++) acc[i][j] = make_float2(0.f, 0.f);

    for (int kt = 0; kt < DIN; kt += 32) {
        __syncthreads();
        #pragma unroll
        for (int it = 0; it < 16; it++) {
            int idx = t + 128 * it;
            int row = idx >> 3;
            int k4  = idx & 7;
            int gn  = node0 + row;
            float4 v = make_float4(0.f, 0.f, 0.f, 0.f);
            if (gn < NN)
                v = *(const float4*)(fbase + (size_t)gn * DIN + kt + k4 * 4);
            *(float4*)&sF[row * FPAD + k4 * 4] = v;
        }
        #pragma unroll
        for (int it = 0; it < 4; it++) {
            int idx = t + 128 * it;
            ((float4*)sW)[idx] = ((const float4*)(wbase + (size_t)kt * DH))[idx];
        }
        __syncthreads();

        #pragma unroll
        for (int k = 0; k < 32; k++) {
            float f[8];
            #pragma unroll
            for (int i = 0; i < 8; i++) f[i] = sF[(rg + 32 * i) * FPAD + k];
            float4 w0 = *(const float4*)&sW[k * 64 + cg * 16 + 0];
            float4 w1 = *(const float4*)&sW[k * 64 + cg * 16 + 4];
            float4 w2 = *(const float4*)&sW[k * 64 + cg * 16 + 8];
            float4 w3 = *(const float4*)&sW[k * 64 + cg * 16 + 12];
            float2 wv[8] = { {w0.x,w0.y},{w0.z,w0.w},{w1.x,w1.y},{w1.z,w1.w},
                             {w2.x,w2.y},{w2.z,w2.w},{w3.x,w3.y},{w3.z,w3.w} };
            #pragma unroll
            for (int i = 0; i < 8; i++) {
                float2 fi = make_float2(f[i], f[i]);
                #pragma unroll
                for (int j = 0; j < 8; j++)
                    acc[i][j] = ffma2(fi, wv[j], acc[i][j]);
            }
        }
    }

    __half* pbase = g_proj + (size_t)m * NN * DH;
    #pragma unroll
    for (int i = 0; i < 8; i++) {
        int n = node0 + rg + 32 * i;
        if (n < NN) {
            __half2* prow = (__half2*)(pbase + (size_t)n * DH + cg * 16);
            union { __half2 h[4]; uint4 u; } pk0, pk1;
            #pragma unroll
            for (int j = 0; j < 4; j++)
                pk0.h[j] = __floats2half2_rn(acc[i][j].x, acc[i][j].y);
            #pragma unroll
            for (int j = 0; j < 4; j++)
                pk1.h[j] = __floats2half2_rn(acc[i][4 + j].x, acc[i][4 + j].y);
            *(uint4*)prow       = pk0.u;
            *((uint4*)prow + 1) = pk1.u;
        }
    }
}

// ---------------- E1: histogram of (m, dst) + per-edge rank ----------------
__global__ void k_hist(const int* __restrict__ dst) {
    int e = blockIdx.x * blockDim.x + threadIdx.x;
    if (e >= EDGES) return;
    int m = blockIdx.y;
    int d = __ldg(dst + (size_t)m * EDGES + e);
    int r = atomicAdd(&g_count[m * NN + d], 1);
    g_rank[(size_t)m * EDGES + e] = (unsigned short)r;
}

// ---------------- E2: two-phase exclusive scan ----------------
__global__ __launch_bounds__(256) void k_scanA() {
    __shared__ int wsum[8];
    const int t = threadIdx.x;
    const long base = (long)blockIdx.x * SCAN_TILE + t * 4;
    int v[4];
    #pragma unroll
    for (int i = 0; i < 4; i++) v[i] = (base + i < NSEG) ? g_count[base + i] : 0;
    int tsum = v[0] + v[1] + v[2] + v[3];

    const int lane = t & 31, w = t >> 5;
    int x = tsum;
    #pragma unroll
    for (int o = 1; o < 32; o <<= 1) {
        int y = __shfl_up_sync(0xffffffffu, x, o);
        if (lane >= o) x += y;
    }
    if (lane == 31) wsum[w] = x;
    __syncthreads();
    if (t < 8) {
        int y = wsum[t];
        #pragma unroll
        for (int o = 1; o < 8; o <<= 1) {
            int z = __shfl_up_sync(0x000000ffu, y, o);
            if (t >= o) y += z;
        }
        wsum[t] = y;
    }
    __syncthreads();
    int run = ((w > 0) ? wsum[w - 1] : 0) + x - tsum;
    #pragma unroll
    for (int i = 0; i < 4; i++) {
        if (base + i < NSEG) g_cursor[base + i] = run;
        run += v[i];
    }
    if (t == 255) g_bsum[blockIdx.x] = wsum[7];
}

__global__ __launch_bounds__(512) void k_scanB() {
    __shared__ int a[512];
    const int t = threadIdx.x;
    int v = (t < NBLK) ? g_bsum[t] : 0;
    a[t] = v;
    __syncthreads();
    #pragma unroll
    for (int o = 1; o < 512; o <<= 1) {
        int x = (t >= o) ? a[t - o] : 0;
        __syncthreads();
        a[t] += x;
        __syncthreads();
    }
    if (t < NBLK) g_bsum[t] = a[t] - v;
}

// ---------------- E3: scatter src ids into CSR order (no atomics) ----------
__global__ void k_scatter(const int* __restrict__ src, const int* __restrict__ dst) {
    int e = blockIdx.x * blockDim.x + threadIdx.x;
    if (e >= EDGES) return;
    int m = blockIdx.y;
    int s   = __ldg(src + (size_t)m * EDGES + e);
    int d   = __ldg(dst + (size_t)m * EDGES + e);
    int rk  = (int)__ldg(&g_rank[(size_t)m * EDGES + e]);
    int seg = m * NN + d;
    int pos = __ldg(&g_cursor[seg]) + __ldg(&g_bsum[seg >> 10]) + rk;
    g_eidx[pos] = s;
}

// ---------------- E4: gather-reduce + mean + bias + prelu + transpose ------
// 8 lanes per segment; each lane owns 8 h-channels (one uint4 of fp16).
// unroll-4: four independent gather chains per thread for MLP.
__global__ void k_aggregate(const float* __restrict__ b,
                            const float* __restrict__ prelu_a) {
    long gt  = (long)blockIdx.x * blockDim.x + threadIdx.x;
    long gid = gt >> 3;
    int lane = (int)(gt & 7);
    if (gid >= (long)NSEG) return;
    int m = (int)(gid / NN);
    int n = (int)(gid % NN);

    int cnt   = g_count[gid];
    int start = g_cursor[gid] + __ldg(&g_bsum[gid >> 10]);
    int end   = start + cnt;

    const uint4* pb = (const uint4*)g_proj + (size_t)m * NN * 8;
    float acc[8] = {0.f,0.f,0.f,0.f,0.f,0.f,0.f,0.f};

    int j = start;
    for (; j + 3 < end; j += 4) {
        int s0 = __ldg(&g_eidx[j]);
        int s1 = __ldg(&g_eidx[j + 1]);
        int s2 = __ldg(&g_eidx[j + 2]);
        int s3 = __ldg(&g_eidx[j + 3]);
        uint4 v0 = __ldg(&pb[(size_t)s0 * 8 + lane]);
        uint4 v1 = __ldg(&pb[(size_t)s1 * 8 + lane]);
        uint4 v2 = __ldg(&pb[(size_t)s2 * 8 + lane]);
        uint4 v3 = __ldg(&pb[(size_t)s3 * 8 + lane]);
        float2 f;
        f = __half22float2(*(__half2*)&v0.x); acc[0]+=f.x; acc[1]+=f.y;
        f = __half22float2(*(__half2*)&v0.y); acc[2]+=f.x; acc[3]+=f.y;
        f = __half22float2(*(__half2*)&v0.z); acc[4]+=f.x; acc[5]+=f.y;
        f = __half22float2(*(__half2*)&v0.w); acc[6]+=f.x; acc[7]+=f.y;
        f = __half22float2(*(__half2*)&v1.x); acc[0]+=f.x; acc[1]+=f.y;
        f = __half22float2(*(__half2*)&v1.y); acc[2]+=f.x; acc[3]+=f.y;
        f = __half22float2(*(__half2*)&v1.z); acc[4]+=f.x; acc[5]+=f.y;
        f = __half22float2(*(__half2*)&v1.w); acc[6]+=f.x; acc[7]+=f.y;
        f = __half22float2(*(__half2*)&v2.x); acc[0]+=f.x; acc[1]+=f.y;
        f = __half22float2(*(__half2*)&v2.y); acc[2]+=f.x; acc[3]+=f.y;
        f = __half22float2(*(__half2*)&v2.z); acc[4]+=f.x; acc[5]+=f.y;
        f = __half22float2(*(__half2*)&v2.w); acc[6]+=f.x; acc[7]+=f.y;
        f = __half22float2(*(__half2*)&v3.x); acc[0]+=f.x; acc[1]+=f.y;
        f = __half22float2(*(__half2*)&v3.y); acc[2]+=f.x; acc[3]+=f.y;
        f = __half22float2(*(__half2*)&v3.z); acc[4]+=f.x; acc[5]+=f.y;
        f = __half22float2(*(__half2*)&v3.w); acc[6]+=f.x; acc[7]+=f.y;
    }
    for (; j < end; j++) {
        int s0 = __ldg(&g_eidx[j]);
        uint4 v0 = __ldg(&pb[(size_t)s0 * 8 + lane]);
        float2 f;
        f = __half22float2(*(__half2*)&v0.x); acc[0]+=f.x; acc[1]+=f.y;
        f = __half22float2(*(__half2*)&v0.y); acc[2]+=f.x; acc[3]+=f.y;
        f = __half22float2(*(__half2*)&v0.z); acc[4]+=f.x; acc[5]+=f.y;
        f = __half22float2(*(__half2*)&v0.w); acc[6]+=f.x; acc[7]+=f.y;
    }

    float inv   = 1.0f / fmaxf((float)cnt, 1.0f);
    float alpha = __ldg(prelu_a + m);
    const float* bp = b + m * DH + lane * 8;
    float h[8];
    #pragma unroll
    for (int c = 0; c < 8; c++) {
        float x = acc[c] * inv + __ldg(bp + c);
        h[c] = x > 0.f ? x : alpha * x;
    }
    union { __half2 p[4]; uint4 u; } pk;
    #pragma unroll
    for (int c = 0; c < 4; c++)
        pk.p[c] = __floats2half2_rn(h[2*c], h[2*c+1]);
    ((uint4*)(g_hn + ((size_t)n * MM + m) * DH))[lane] = pk.u;
}

// ---------------- K4: logits[m] = sum_n tanh(h @ fcW + fcb) . attn / N ----
// 256 threads, 256 rows/block. No hn staging: stream fp16 rows from L2 in
// k-chunks of 8; 4 adjacent threads (cg) share a row -> L1 broadcast.
// Thread tile: 4 rows (stride 64) x 16 cols. Only fc_W in smem (16 KB).
__global__ __launch_bounds__(256) void k_attnlogits(const float* __restrict__ fc_W,
                                                    const float* __restrict__ fc_b,
                                                    const float* __restrict__ attn) {
    __shared__ float sW[64 * 64];
    __shared__ float sPart[3];

    const int t = threadIdx.x;
    const int rg = t >> 2;      // 0..63
    const int cg = t & 3;
    const long p0 = (long)blockIdx.x * 256;

    if (t < 3) sPart[t] = 0.f;
    #pragma unroll
    for (int it = 0; it < 4; it++) {
        int idx = t + 256 * it;
        ((float4*)sW)[idx] = ((const float4*)fc_W)[idx];
    }
    __syncthreads();

    const uint4* hb = (const uint4*)g_hn;   // 8 halfs per uint4
    long rowp[4];
    bool rowok[4];
    #pragma unroll
    for (int i = 0; i < 4; i++) {
        rowp[i]  = p0 + rg + 64 * i;
        rowok[i] = rowp[i] < (long)NSEG;
    }

    float2 acc[4][8];
    #pragma unroll
    for (int i = 0; i < 4; i++)
        #pragma unroll
        for (int j = 0; j < 8; j++) acc[i][j] = make_float2(0.f, 0.f);

    #pragma unroll
    for (int kc = 0; kc < 8; kc++) {        // k-chunks of 8
        uint4 hv[4];
        #pragma unroll
        for (int i = 0; i < 4; i++)
            hv[i] = rowok[i] ? __ldg(&hb[rowp[i] * 8 + kc])
                             : make_uint4(0u, 0u, 0u, 0u);
        float f[4][8];
        #pragma unroll
        for (int i = 0; i < 4; i++) {
            float2 x;
            x = __half22float2(((const __half2*)&hv[i])[0]); f[i][0]=x.x; f[i][1]=x.y;
            x = __half22float2(((const __half2*)&hv[i])[1]); f[i][2]=x.x; f[i][3]=x.y;
            x = __half22float2(((const __half2*)&hv[i])[2]); f[i][4]=x.x; f[i][5]=x.y;
            x = __half22float2(((const __half2*)&hv[i])[3]); f[i][6]=x.x; f[i][7]=x.y;
        }
        #pragma unroll
        for (int kk = 0; kk < 8; kk++) {
            int k = kc * 8 + kk;
            float4 w0 = *(const float4*)&sW[k * 64 + cg * 16 + 0];
            float4 w1 = *(const float4*)&sW[k * 64 + cg * 16 + 4];
            float4 w2 = *(const float4*)&sW[k * 64 + cg * 16 + 8];
            float4 w3 = *(const float4*)&sW[k * 64 + cg * 16 + 12];
            float2 wv[8] = { {w0.x,w0.y},{w0.z,w0.w},{w1.x,w1.y},{w1.z,w1.w},
                             {w2.x,w2.y},{w2.z,w2.w},{w3.x,w3.y},{w3.z,w3.w} };
            #pragma unroll
            for (int i = 0; i < 4; i++) {
                float2 fi = make_float2(f[i][kk], f[i][kk]);
                #pragma unroll
                for (int j = 0; j < 8; j++)
                    acc[i][j] = ffma2(fi, wv[j], acc[i][j]);
            }
        }
    }

    const float2* fb2 = (const float2*)fc_b;
    const float2* av2 = (const float2*)attn;
    float c0 = 0.f, c1 = 0.f, c2 = 0.f;
    #pragma unroll
    for (int i = 0; i < 4; i++) {
        float ci = 0.f;
        #pragma unroll
        for (int j = 0; j < 8; j++) {
            float2 bb = __ldg(fb2 + cg * 8 + j);
            float2 aa = __ldg(av2 + cg * 8 + j);
            ci += tanhf(acc[i][j].x + bb.x) * aa.x
                + tanhf(acc[i][j].y + bb.y) * aa.y;
        }
        ci += __shfl_xor_sync(0xffffffffu, ci, 1);
        ci += __shfl_xor_sync(0xffffffffu, ci, 2);
        if (cg == 0 && rowok[i]) {
            int mi = (int)(rowp[i] % 3);
            if (mi == 0) c0 += ci; else if (mi == 1) c1 += ci; else c2 += ci;
        }
    }
    if (cg == 0) {
        if (c0 != 0.f) atomicAdd(&sPart[0], c0);
        if (c1 != 0.f) atomicAdd(&sPart[1], c1);
        if (c2 != 0.f) atomicAdd(&sPart[2], c2);
    }
    __syncthreads();
    if (t < 3) atomicAdd(&g_logits[t], sPart[t] * (1.0f / (float)NN));
}

// ---------------- K5: softmax(logits) + z = sum_m beta_m * hn[:,m,:] -------
__global__ void k_combine(float* __restrict__ out) {
    const long tid = (long)blockIdx.x * blockDim.x + threadIdx.x;
    if (tid >= (long)NN * 8) return;
    const int  q = (int)(tid & 7);
    const long n = tid >> 3;

    float l0 = g_logits[0], l1 = g_logits[1], l2 = g_logits[2];
    float mx = fmaxf(l0, fmaxf(l1, l2));
    float e0 = __expf(l0 - mx), e1 = __expf(l1 - mx), e2 = __expf(l2 - mx);
    float is = 1.0f / (e0 + e1 + e2);
    float b0 = e0 * is, b1 = e1 * is, b2 = e2 * is;

    const uint4* r = (const uint4*)(g_hn + (size_t)n * (MM * DH)) + q;
    uint4 u0 = __ldg(r), u1 = __ldg(r + 8), u2 = __ldg(r + 16);

    float o[8];
    #pragma unroll
    for (int c = 0; c < 4; c++) {
        float2 f0 = __half22float2(((const __half2*)&u0)[c]);
        float2 f1 = __half22float2(((const __half2*)&u1)[c]);
        float2 f2 = __half22float2(((const __half2*)&u2)[c]);
        o[2*c]   = b0 * f0.x + b1 * f1.x + b2 * f2.x;
        o[2*c+1] = b0 * f0.y + b1 * f1.y + b2 * f2.y;
    }
    float* op = out + (size_t)n * DH + q * 8;
    *(float4*)op       = make_float4(o[0], o[1], o[2], o[3]);
    *(float4*)(op + 4) = make_float4(o[4], o[5], o[6], o[7]);
}

// ---------------- launcher (fork-join: sort pipeline ∥ proj) ----------------
static cudaStream_t s_side = nullptr;
static cudaEvent_t  s_evFork = nullptr, s_evJoin = nullptr;

extern "C" void kernel_launch(void* const* d_in, const int* in_sizes, int n_in,
                              void* d_out, int out_size) {
    const float* feats   = (const float*)d_in[0];
    const int*   src     = (const int*)  d_in[1];
    const int*   dst     = (const int*)  d_in[2];
    const float* W       = (const float*)d_in[3];
    const float* b       = (const float*)d_in[4];
    const float* prelu_a = (const float*)d_in[5];
    const float* fc_W    = (const float*)d_in[6];
    const float* fc_b    = (const float*)d_in[7];
    const float* attn    = (const float*)d_in[8];
    float* out = (float*)d_out;

    if (!s_side) {
        cudaStreamCreateWithFlags(&s_side, cudaStreamNonBlocking);
        cudaEventCreateWithFlags(&s_evFork, cudaEventDisableTiming);
        cudaEventCreateWithFlags(&s_evJoin, cudaEventDisableTiming);
    }

    void *p_cnt, *p_log;
    cudaGetSymbolAddress(&p_cnt, g_count);
    cudaGetSymbolAddress(&p_log, g_logits);

    // fork: sort pipeline on side stream
    cudaEventRecord(s_evFork, 0);
    cudaStreamWaitEvent(s_side, s_evFork, 0);

    cudaMemsetAsync(p_cnt, 0, sizeof(int) * NSEG, s_side);
    dim3 ge((EDGES + 255) / 256, MM);
    k_hist   <<<ge, 256, 0, s_side>>>(dst);
    k_scanA  <<<NBLK, 256, 0, s_side>>>();
    k_scanB  <<<1, 512, 0, s_side>>>();
    k_scatter<<<ge, 256, 0, s_side>>>(src, dst);
    cudaEventRecord(s_evJoin, s_side);

    // main stream: projection GEMM (+ logits clear)
    cudaMemsetAsync(p_log, 0, sizeof(float) * MM, 0);
    dim3 g1((NN + 255) / 256, MM);
    k_proj<<<g1, 128>>>(feats, W);

    // join, then aggregate -> attnlogits -> combine
    cudaStreamWaitEvent(0, s_evJoin, 0);

    const long nagg = (long)NSEG * 8;
    k_aggregate<<<(unsigned)((nagg + 255) / 256), 256>>>(b, prelu_a);

    k_attnlogits<<<(unsigned)((NSEG + 255) / 256), 256>>>(fc_W, fc_b, attn);

    k_combine<<<(unsigned)(((long)NN * 8 + 255) / 256), 256>>>(out);
}

// round 7
// speedup vs baseline: 1.3936x; 1.1968x over previous
#include <cuda_runtime.h>
#include <cuda_fp16.h>
#include <cstdint>
#include <cstddef>

#define MM    3
#define NN    100000
#define DIN   128
#define DH    64
#define EDGES 1600000
#define NSEG  (MM * NN)                 // 300000 segments (m, dst)
#define SCAN_TILE 1024
#define NBLK  ((NSEG + SCAN_TILE - 1) / SCAN_TILE)   // 293

// ---------------- scratch (device globals; no allocations) ----------------
__device__ __half g_proj[(size_t)MM * NN * DH];  // 38.4 MB [m][n][h] fp16
__device__ __half g_hn  [(size_t)NN * MM * DH];  // 38.4 MB [n][m][h] fp16
__device__ int    g_count [NSEG];
__device__ int    g_cursor[NSEG];
__device__ int    g_eidx[(size_t)MM * EDGES];
__device__ unsigned short g_rank[(size_t)MM * EDGES];
__device__ int    g_bsum[NBLK];
__device__ float  g_logits[MM];

// packed f32x2 FMA (FFMA2) — 2x fp32 FMA throughput, only reachable via PTX
__device__ __forceinline__ float2 ffma2(float2 a, float2 b, float2 c) {
    unsigned long long au = *reinterpret_cast<unsigned long long*>(&a);
    unsigned long long bu = *reinterpret_cast<unsigned long long*>(&b);
    unsigned long long cu = *reinterpret_cast<unsigned long long*>(&c);
    unsigned long long du;
    asm("fma.rn.f32x2 %0, %1, %2, %3;" : "=l"(du) : "l"(au), "l"(bu), "l"(cu));
    return *reinterpret_cast<float2*>(&du);
}

// HW tanh (single MUFU op on sm_75+) — replaces ~25-instr software tanhf
__device__ __forceinline__ float tanh_hw(float x) {
    float y;
    asm("tanh.approx.f32 %0, %1;" : "=f"(y) : "f"(x));
    return y;
}

// ---------------- K1: proj[m] = feats[m] @ W[m]  (fp32 math, fp16 store) ---
#define FPAD 36
__global__ __launch_bounds__(128) void k_proj(const float* __restrict__ feats,
                                              const float* __restrict__ W) {
    __shared__ float sF[256 * FPAD];
    __shared__ float sW[32 * 64];

    const int m     = blockIdx.y;
    const int node0 = blockIdx.x * 256;
    const int t  = threadIdx.x;
    const int rg = t >> 2;
    const int cg = t & 3;

    const float* fbase = feats + (size_t)m * NN * DIN;
    const float* wbase = W     + (size_t)m * DIN * DH;

    float2 acc[8][8];
    #pragma unroll
    for (int i = 0; i < 8; i++)
        #pragma unroll
        for (int j = 0; j < 8; j++) acc[i][j] = make_float2(0.f, 0.f);

    for (int kt = 0; kt < DIN; kt += 32) {
        __syncthreads();
        #pragma unroll
        for (int it = 0; it < 16; it++) {
            int idx = t + 128 * it;
            int row = idx >> 3;
            int k4  = idx & 7;
            int gn  = node0 + row;
            float4 v = make_float4(0.f, 0.f, 0.f, 0.f);
            if (gn < NN)
                v = *(const float4*)(fbase + (size_t)gn * DIN + kt + k4 * 4);
            *(float4*)&sF[row * FPAD + k4 * 4] = v;
        }
        #pragma unroll
        for (int it = 0; it < 4; it++) {
            int idx = t + 128 * it;
            ((float4*)sW)[idx] = ((const float4*)(wbase + (size_t)kt * DH))[idx];
        }
        __syncthreads();

        #pragma unroll
        for (int k = 0; k < 32; k++) {
            float f[8];
            #pragma unroll
            for (int i = 0; i < 8; i++) f[i] = sF[(rg + 32 * i) * FPAD + k];
            float4 w0 = *(const float4*)&sW[k * 64 + cg * 16 + 0];
            float4 w1 = *(const float4*)&sW[k * 64 + cg * 16 + 4];
            float4 w2 = *(const float4*)&sW[k * 64 + cg * 16 + 8];
            float4 w3 = *(const float4*)&sW[k * 64 + cg * 16 + 12];
            float2 wv[8] = { {w0.x,w0.y},{w0.z,w0.w},{w1.x,w1.y},{w1.z,w1.w},
                             {w2.x,w2.y},{w2.z,w2.w},{w3.x,w3.y},{w3.z,w3.w} };
            #pragma unroll
            for (int i = 0; i < 8; i++) {
                float2 fi = make_float2(f[i], f[i]);
                #pragma unroll
                for (int j = 0; j < 8; j++)
                    acc[i][j] = ffma2(fi, wv[j], acc[i][j]);
            }
        }
    }

    __half* pbase = g_proj + (size_t)m * NN * DH;
    #pragma unroll
    for (int i = 0; i < 8; i++) {
        int n = node0 + rg + 32 * i;
        if (n < NN) {
            __half2* prow = (__half2*)(pbase + (size_t)n * DH + cg * 16);
            union { __half2 h[4]; uint4 u; } pk0, pk1;
            #pragma unroll
            for (int j = 0; j < 4; j++)
                pk0.h[j] = __floats2half2_rn(acc[i][j].x, acc[i][j].y);
            #pragma unroll
            for (int j = 0; j < 4; j++)
                pk1.h[j] = __floats2half2_rn(acc[i][4 + j].x, acc[i][4 + j].y);
            *(uint4*)prow       = pk0.u;
            *((uint4*)prow + 1) = pk1.u;
        }
    }
}

// ---------------- E1: histogram of (m, dst) + per-edge rank ----------------
__global__ void k_hist(const int* __restrict__ dst) {
    int e = blockIdx.x * blockDim.x + threadIdx.x;
    if (e >= EDGES) return;
    int m = blockIdx.y;
    int d = __ldg(dst + (size_t)m * EDGES + e);
    int r = atomicAdd(&g_count[m * NN + d], 1);
    g_rank[(size_t)m * EDGES + e] = (unsigned short)r;
}

// ---------------- E2: two-phase exclusive scan ----------------
__global__ __launch_bounds__(256) void k_scanA() {
    __shared__ int wsum[8];
    const int t = threadIdx.x;
    const long base = (long)blockIdx.x * SCAN_TILE + t * 4;
    int v[4];
    #pragma unroll
    for (int i = 0; i < 4; i++) v[i] = (base + i < NSEG) ? g_count[base + i] : 0;
    int tsum = v[0] + v[1] + v[2] + v[3];

    const int lane = t & 31, w = t >> 5;
    int x = tsum;
    #pragma unroll
    for (int o = 1; o < 32; o <<= 1) {
        int y = __shfl_up_sync(0xffffffffu, x, o);
        if (lane >= o) x += y;
    }
    if (lane == 31) wsum[w] = x;
    __syncthreads();
    if (t < 8) {
        int y = wsum[t];
        #pragma unroll
        for (int o = 1; o < 8; o <<= 1) {
            int z = __shfl_up_sync(0x000000ffu, y, o);
            if (t >= o) y += z;
        }
        wsum[t] = y;
    }
    __syncthreads();
    int run = ((w > 0) ? wsum[w - 1] : 0) + x - tsum;
    #pragma unroll
    for (int i = 0; i < 4; i++) {
        if (base + i < NSEG) g_cursor[base + i] = run;
        run += v[i];
    }
    if (t == 255) g_bsum[blockIdx.x] = wsum[7];
}

__global__ __launch_bounds__(512) void k_scanB() {
    __shared__ int a[512];
    const int t = threadIdx.x;
    int v = (t < NBLK) ? g_bsum[t] : 0;
    a[t] = v;
    __syncthreads();
    #pragma unroll
    for (int o = 1; o < 512; o <<= 1) {
        int x = (t >= o) ? a[t - o] : 0;
        __syncthreads();
        a[t] += x;
        __syncthreads();
    }
    if (t < NBLK) g_bsum[t] = a[t] - v;
}

// ---------------- E3: scatter src ids into CSR order (no atomics) ----------
__global__ void k_scatter(const int* __restrict__ src, const int* __restrict__ dst) {
    int e = blockIdx.x * blockDim.x + threadIdx.x;
    if (e >= EDGES) return;
    int m = blockIdx.y;
    int s   = __ldg(src + (size_t)m * EDGES + e);
    int d   = __ldg(dst + (size_t)m * EDGES + e);
    int rk  = (int)__ldg(&g_rank[(size_t)m * EDGES + e]);
    int seg = m * NN + d;
    int pos = __ldg(&g_cursor[seg]) + __ldg(&g_bsum[seg >> 10]) + rk;
    g_eidx[pos] = s;
}

// ---------------- E4: gather-reduce + mean + bias + prelu + transpose ------
// 8 lanes per segment; each lane owns 8 h-channels (one uint4 of fp16).
// unroll-2 (round-4 proven config).
__global__ void k_aggregate(const float* __restrict__ b,
                            const float* __restrict__ prelu_a) {
    long gt  = (long)blockIdx.x * blockDim.x + threadIdx.x;
    long gid = gt >> 3;
    int lane = (int)(gt & 7);
    if (gid >= (long)NSEG) return;
    int m = (int)(gid / NN);
    int n = (int)(gid % NN);

    int cnt   = g_count[gid];
    int start = g_cursor[gid] + __ldg(&g_bsum[gid >> 10]);
    int end   = start + cnt;

    const uint4* pb = (const uint4*)g_proj + (size_t)m * NN * 8;
    float acc[8] = {0.f,0.f,0.f,0.f,0.f,0.f,0.f,0.f};

    int j = start;
    for (; j + 1 < end; j += 2) {
        int s0 = __ldg(&g_eidx[j]);
        int s1 = __ldg(&g_eidx[j + 1]);
        uint4 v0 = __ldg(&pb[(size_t)s0 * 8 + lane]);
        uint4 v1 = __ldg(&pb[(size_t)s1 * 8 + lane]);
        float2 f;
        f = __half22float2(*(__half2*)&v0.x); acc[0]+=f.x; acc[1]+=f.y;
        f = __half22float2(*(__half2*)&v0.y); acc[2]+=f.x; acc[3]+=f.y;
        f = __half22float2(*(__half2*)&v0.z); acc[4]+=f.x; acc[5]+=f.y;
        f = __half22float2(*(__half2*)&v0.w); acc[6]+=f.x; acc[7]+=f.y;
        f = __half22float2(*(__half2*)&v1.x); acc[0]+=f.x; acc[1]+=f.y;
        f = __half22float2(*(__half2*)&v1.y); acc[2]+=f.x; acc[3]+=f.y;
        f = __half22float2(*(__half2*)&v1.z); acc[4]+=f.x; acc[5]+=f.y;
        f = __half22float2(*(__half2*)&v1.w); acc[6]+=f.x; acc[7]+=f.y;
    }
    if (j < end) {
        int s0 = __ldg(&g_eidx[j]);
        uint4 v0 = __ldg(&pb[(size_t)s0 * 8 + lane]);
        float2 f;
        f = __half22float2(*(__half2*)&v0.x); acc[0]+=f.x; acc[1]+=f.y;
        f = __half22float2(*(__half2*)&v0.y); acc[2]+=f.x; acc[3]+=f.y;
        f = __half22float2(*(__half2*)&v0.z); acc[4]+=f.x; acc[5]+=f.y;
        f = __half22float2(*(__half2*)&v0.w); acc[6]+=f.x; acc[7]+=f.y;
    }

    float inv   = 1.0f / fmaxf((float)cnt, 1.0f);
    float alpha = __ldg(prelu_a + m);
    const float* bp = b + m * DH + lane * 8;
    float h[8];
    #pragma unroll
    for (int c = 0; c < 8; c++) {
        float x = acc[c] * inv + __ldg(bp + c);
        h[c] = x > 0.f ? x : alpha * x;
    }
    union { __half2 p[4]; uint4 u; } pk;
    #pragma unroll
    for (int c = 0; c < 4; c++)
        pk.p[c] = __floats2half2_rn(h[2*c], h[2*c+1]);
    ((uint4*)(g_hn + ((size_t)n * MM + m) * DH))[lane] = pk.u;
}

// ---------------- K4: logits[m] = sum_n tanh(h @ fcW + fcb) . attn / N ----
// 128 threads, 256 rows/block, thread tile 8 rows (stride 32) x 16 cols.
// (round-4 proven config; tanhf -> HW tanh.approx)
#define HPAD 68
__global__ __launch_bounds__(128) void k_attnlogits(const float* __restrict__ fc_W,
                                                    const float* __restrict__ fc_b,
                                                    const float* __restrict__ attn) {
    extern __shared__ float dynsm[];
    float* sH = dynsm;                 // 256 x HPAD
    float* sW = dynsm + 256 * HPAD;    // 64 x 64
    __shared__ float sPart[3];

    const int t = threadIdx.x;
    const int rg = t >> 2;
    const int cg = t & 3;
    const long p0 = (long)blockIdx.x * 256;

    if (t < 3) sPart[t] = 0.f;

    // load 256 fp16 rows: 2048 uint4 (8 halfs each) / 128 thr = 16 each
    #pragma unroll
    for (int it = 0; it < 16; it++) {
        int idx = t + 128 * it;
        int row = idx >> 3;
        int k8  = idx & 7;
        long p  = p0 + row;
        uint4 v = make_uint4(0u, 0u, 0u, 0u);
        if (p < (long)NSEG)
            v = *((const uint4*)(g_hn + (size_t)p * DH) + k8);
        float* dstp = &sH[row * HPAD + k8 * 8];
        float2 f0 = __half22float2(*(__half2*)&v.x);
        float2 f1 = __half22float2(*(__half2*)&v.y);
        float2 f2 = __half22float2(*(__half2*)&v.z);
        float2 f3 = __half22float2(*(__half2*)&v.w);
        dstp[0] = f0.x; dstp[1] = f0.y; dstp[2] = f1.x; dstp[3] = f1.y;
        dstp[4] = f2.x; dstp[5] = f2.y; dstp[6] = f3.x; dstp[7] = f3.y;
    }
    #pragma unroll
    for (int it = 0; it < 8; it++) {
        int idx = t + 128 * it;
        ((float4*)sW)[idx] = ((const float4*)fc_W)[idx];
    }
    __syncthreads();

    float2 acc[8][8];
    #pragma unroll
    for (int i = 0; i < 8; i++)
        #pragma unroll
        for (int j = 0; j < 8; j++) acc[i][j] = make_float2(0.f, 0.f);

    #pragma unroll 8
    for (int k = 0; k < DH; k++) {
        float f[8];
        #pragma unroll
        for (int i = 0; i < 8; i++) f[i] = sH[(rg + 32 * i) * HPAD + k];
        float4 w0 = *(const float4*)&sW[k * 64 + cg * 16 + 0];
        float4 w1 = *(const float4*)&sW[k * 64 + cg * 16 + 4];
        float4 w2 = *(const float4*)&sW[k * 64 + cg * 16 + 8];
        float4 w3 = *(const float4*)&sW[k * 64 + cg * 16 + 12];
        float2 wv[8] = { {w0.x,w0.y},{w0.z,w0.w},{w1.x,w1.y},{w1.z,w1.w},
                         {w2.x,w2.y},{w2.z,w2.w},{w3.x,w3.y},{w3.z,w3.w} };
        #pragma unroll
        for (int i = 0; i < 8; i++) {
            float2 fi = make_float2(f[i], f[i]);
            #pragma unroll
            for (int j = 0; j < 8; j++)
                acc[i][j] = ffma2(fi, wv[j], acc[i][j]);
        }
    }

    const float2* fb2 = (const float2*)fc_b;
    const float2* av2 = (const float2*)attn;
    float c0 = 0.f, c1 = 0.f, c2 = 0.f;
    #pragma unroll
    for (int i = 0; i < 8; i++) {
        long p = p0 + rg + 32 * i;
        float ci = 0.f;
        #pragma unroll
        for (int j = 0; j < 8; j++) {
            float2 bb = __ldg(fb2 + cg * 8 + j);
            float2 aa = __ldg(av2 + cg * 8 + j);
            ci += tanh_hw(acc[i][j].x + bb.x) * aa.x
                + tanh_hw(acc[i][j].y + bb.y) * aa.y;
        }
        ci += __shfl_xor_sync(0xffffffffu, ci, 1);
        ci += __shfl_xor_sync(0xffffffffu, ci, 2);
        if (cg == 0 && p < (long)NSEG) {
            int mi = (int)(p % 3);
            if (mi == 0) c0 += ci; else if (mi == 1) c1 += ci; else c2 += ci;
        }
    }
    if (cg == 0) {
        atomicAdd(&sPart[0], c0);
        atomicAdd(&sPart[1], c1);
        atomicAdd(&sPart[2], c2);
    }
    __syncthreads();
    if (t < 3) atomicAdd(&g_logits[t], sPart[t] * (1.0f / (float)NN));
}

// ---------------- K5: softmax(logits) + z = sum_m beta_m * hn[:,m,:] -------
__global__ void k_combine(float* __restrict__ out) {
    const long tid = (long)blockIdx.x * blockDim.x + threadIdx.x;
    if (tid >= (long)NN * 8) return;
    const int  q = (int)(tid & 7);
    const long n = tid >> 3;

    float l0 = g_logits[0], l1 = g_logits[1], l2 = g_logits[2];
    float mx = fmaxf(l0, fmaxf(l1, l2));
    float e0 = __expf(l0 - mx), e1 = __expf(l1 - mx), e2 = __expf(l2 - mx);
    float is = 1.0f / (e0 + e1 + e2);
    float b0 = e0 * is, b1 = e1 * is, b2 = e2 * is;

    const uint4* r = (const uint4*)(g_hn + (size_t)n * (MM * DH)) + q;
    uint4 u0 = __ldg(r), u1 = __ldg(r + 8), u2 = __ldg(r + 16);

    float o[8];
    #pragma unroll
    for (int c = 0; c < 4; c++) {
        float2 f0 = __half22float2(((const __half2*)&u0)[c]);
        float2 f1 = __half22float2(((const __half2*)&u1)[c]);
        float2 f2 = __half22float2(((const __half2*)&u2)[c]);
        o[2*c]   = b0 * f0.x + b1 * f1.x + b2 * f2.x;
        o[2*c+1] = b0 * f0.y + b1 * f1.y + b2 * f2.y;
    }
    float* op = out + (size_t)n * DH + q * 8;
    *(float4*)op       = make_float4(o[0], o[1], o[2], o[3]);
    *(float4*)(op + 4) = make_float4(o[4], o[5], o[6], o[7]);
}

// ---------------- launcher (fork-join: sort pipeline ∥ proj) ----------------
static cudaStream_t s_side = nullptr;
static cudaEvent_t  s_evFork = nullptr, s_evJoin = nullptr;

extern "C" void kernel_launch(void* const* d_in, const int* in_sizes, int n_in,
                              void* d_out, int out_size) {
    const float* feats   = (const float*)d_in[0];
    const int*   src     = (const int*)  d_in[1];
    const int*   dst     = (const int*)  d_in[2];
    const float* W       = (const float*)d_in[3];
    const float* b       = (const float*)d_in[4];
    const float* prelu_a = (const float*)d_in[5];
    const float* fc_W    = (const float*)d_in[6];
    const float* fc_b    = (const float*)d_in[7];
    const float* attn    = (const float*)d_in[8];
    float* out = (float*)d_out;

    if (!s_side) {
        cudaStreamCreateWithFlags(&s_side, cudaStreamNonBlocking);
        cudaEventCreateWithFlags(&s_evFork, cudaEventDisableTiming);
        cudaEventCreateWithFlags(&s_evJoin, cudaEventDisableTiming);
    }

    void *p_cnt, *p_log;
    cudaGetSymbolAddress(&p_cnt, g_count);
    cudaGetSymbolAddress(&p_log, g_logits);

    const int attn_smem = 256 * HPAD * 4 + 64 * 64 * 4;   // 86016
    cudaFuncSetAttribute(k_attnlogits,
                         cudaFuncAttributeMaxDynamicSharedMemorySize, attn_smem);

    // fork: sort pipeline on side stream
    cudaEventRecord(s_evFork, 0);
    cudaStreamWaitEvent(s_side, s_evFork, 0);

    cudaMemsetAsync(p_cnt, 0, sizeof(int) * NSEG, s_side);
    dim3 ge((EDGES + 255) / 256, MM);
    k_hist   <<<ge, 256, 0, s_side>>>(dst);
    k_scanA  <<<NBLK, 256, 0, s_side>>>();
    k_scanB  <<<1, 512, 0, s_side>>>();
    k_scatter<<<ge, 256, 0, s_side>>>(src, dst);
    cudaEventRecord(s_evJoin, s_side);

    // main stream: projection GEMM (+ logits clear)
    cudaMemsetAsync(p_log, 0, sizeof(float) * MM, 0);
    dim3 g1((NN + 255) / 256, MM);
    k_proj<<<g1, 128>>>(feats, W);

    // join, then aggregate -> attnlogits -> combine
    cudaStreamWaitEvent(0, s_evJoin, 0);

    const long nagg = (long)NSEG * 8;
    k_aggregate<<<(unsigned)((nagg + 255) / 256), 256>>>(b, prelu_a);

    k_attnlogits<<<(unsigned)((NSEG + 255) / 256), 128, attn_smem>>>(fc_W, fc_b, attn);

    k_combine<<<(unsigned)(((long)NN * 8 + 255) / 256), 256>>>(out);
}